// round 7
// baseline (speedup 1.0000x reference)
#include <cuda_runtime.h>
#include <math.h>

#define SLEN 256
#define BATCH 16384
#define PI_F 3.14159265358979323846f
#define R2_F 0.70710678118654752440f

typedef unsigned long long ull;

// ---------- packed f32x2 primitives ----------
__device__ __forceinline__ ull F2MUL(ull a, ull b) {
    ull d; asm("mul.rn.f32x2 %0,%1,%2;" : "=l"(d) : "l"(a), "l"(b)); return d;
}
__device__ __forceinline__ ull F2FMA(ull a, ull b, ull c) {
    ull d; asm("fma.rn.f32x2 %0,%1,%2,%3;" : "=l"(d) : "l"(a), "l"(b), "l"(c)); return d;
}
__device__ __forceinline__ ull F2SUB(ull a, ull b) {
    ull d; asm("sub.rn.f32x2 %0,%1,%2;" : "=l"(d) : "l"(a), "l"(b)); return d;
}
__device__ __forceinline__ ull PACK2(float lo, float hi) {
    ull d; asm("mov.b64 %0,{%1,%2};" : "=l"(d) : "f"(lo), "f"(hi)); return d;
}
__device__ __forceinline__ float2 UNPK(ull v) {
    float2 r; asm("mov.b64 {%0,%1},%2;" : "=f"(r.x), "=f"(r.y) : "l"(v)); return r;
}
__device__ __forceinline__ ull SWAPH(ull v) {
    float2 r = UNPK(v); return PACK2(r.y, r.x);
}
__device__ __forceinline__ ull MIXLH(ull a, ull b) {   // (a.lo, b.hi)
    float2 x = UNPK(a), y = UNPK(b); return PACK2(x.x, y.y);
}
__device__ __forceinline__ ull SHFL64(ull v) {
    return __shfl_xor_sync(0xFFFFFFFFu, v, 1);
}
__device__ __forceinline__ ull HIXCH(ull v) {  // exchange hi lane with partner thread
    float2 f = UNPK(v);
    f.y = __shfl_xor_sync(0xFFFFFFFFu, f.y, 1);
    return PACK2(f.x, f.y);
}

// ---------- precomputed constants ----------
// L2a (a=0,l=1, H-folded) general rot, round-4 42-slot format
__device__ float2 g_l2a[42];
// constant diagonals: [p][ C0..3 | S0..3 | nS0..3 ] (12 float2 per parity)
__device__ float2 g_d1[24];
__device__ float2 g_d2[24];
// phase offsets: [diag 0/1][slot s=q0*8+q1*4+q2*2+q3] (16 each)
__device__ float g_off[32];
// RY coefs: [layer m=0(1a),1(1b),2(2b)][q][c,s]
__device__ float g_ryf[24];
// KAN folded weights
__device__ float g_kan[140];

__global__ void setup_kernel(const float* __restrict__ p1, const float* __restrict__ p2,
                             const float* __restrict__ base_w, const float* __restrict__ spline_w) {
    int t = threadIdx.x;
    if (t == 0) {
        // ---- L2a: a=0, l=1 rots with H fold, round-4 packing ----
        for (int q = 0; q < 4; q++) {
            float phi = p1[12 + q * 3 + 0];
            float th  = p1[12 + q * 3 + 1];
            float om  = p1[12 + q * 3 + 2];
            float st, ct; sincosf(0.5f * th, &st, &ct);
            float sp, cp; sincosf(0.5f * (phi + om), &sp, &cp);
            float sm, cm; sincosf(0.5f * (phi - om), &sm, &cm);
            float ar =  cp * ct, ai = -sp * ct;
            float br = -cm * st, bi = -sm * st;
            float dr =  cm * st, di = -sm * st;
            float er =  cp * ct, ei =  sp * ct;
            // fold inter-ansatz H: Rot' = H @ Rot
            float nar = (ar + dr) * R2_F, nai = (ai + di) * R2_F;
            float nbr = (br + er) * R2_F, nbi = (bi + ei) * R2_F;
            float ndr = (ar - dr) * R2_F, ndi = (ai - di) * R2_F;
            float ner = (br - er) * R2_F, nei = (bi - ei) * R2_F;
            ar = nar; ai = nai; br = nbr; bi = nbi;
            dr = ndr; di = ndi; er = ner; ei = nei;
            float2* base = g_l2a;
            if (q == 0) {
                base[0] = make_float2(ar, ar);   base[1] = make_float2(-ai, -ai);
                base[2] = make_float2(ai, ai);   base[3] = make_float2(br, br);
                base[4] = make_float2(-bi, -bi); base[5] = make_float2(bi, bi);
                base[6] = make_float2(er, er);   base[7] = make_float2(-ei, -ei);
                base[8] = make_float2(ei, ei);   base[9] = make_float2(dr, dr);
                base[10] = make_float2(-di, -di); base[11] = make_float2(di, di);
            } else if (q == 1 || q == 2) {
                float2* o = base + (q == 1 ? 12 : 24);
                o[0]  = make_float2(ar, ar);   o[1]  = make_float2(-ai, -ai);
                o[2]  = make_float2(br, br);   o[3]  = make_float2(-bi, -bi);
                o[4]  = make_float2(ai, ai);   o[5]  = make_float2(bi, bi);
                o[6]  = make_float2(dr, dr);   o[7]  = make_float2(-di, -di);
                o[8]  = make_float2(er, er);   o[9]  = make_float2(-ei, -ei);
                o[10] = make_float2(di, di);   o[11] = make_float2(ei, ei);
            } else {
                float2* o = base + 36;
                o[0] = make_float2(ar, er);
                o[1] = make_float2(br, dr);
                o[2] = make_float2(-ai, -ei);
                o[3] = make_float2(-bi, -di);
                o[4] = make_float2(ai, ei);
                o[5] = make_float2(bi, di);
            }
        }
        // ---- RY coefficients for layers 1a(a0l0), 1b(a1l0), 2b(a1l1) ----
        for (int m = 0; m < 3; m++) {
            int a = (m == 0) ? 0 : 1;
            int l = (m == 2) ? 1 : 0;
            const float* pp = a ? p2 : p1;
            for (int q = 0; q < 4; q++) {
                float th = pp[l * 12 + q * 3 + 1];
                g_ryf[m * 8 + q * 2 + 0] = cosf(0.5f * th);
                g_ryf[m * 8 + q * 2 + 1] = sinf(0.5f * th);
            }
        }
        // ---- phase offsets: Dphi of 1a (into D1) and of 1b (into D2) ----
        for (int d = 0; d < 2; d++) {
            const float* pp = d ? p2 : p1;   // phi of layer (a=d, l=0)
            float f0 = 0.5f * pp[0], f1 = 0.5f * pp[3], f2 = 0.5f * pp[6], f3 = 0.5f * pp[9];
            for (int s = 0; s < 16; s++) {
                int q0 = (s >> 3) & 1, q1 = (s >> 2) & 1, q2 = (s >> 1) & 1, q3 = s & 1;
                g_off[d * 16 + s] = (q0 ? f0 : -f0) + (q1 ? f1 : -f1)
                                  + (q2 ? f2 : -f2) + (q3 ? f3 : -f3);
            }
        }
        // ---- Dc1: Domega of 1a ----
        {
            float w0 = 0.5f * p1[2], w1 = 0.5f * p1[5], w2 = 0.5f * p1[8], w3 = 0.5f * p1[11];
            float ph[16];
            for (int s = 0; s < 16; s++) {
                int q0 = (s >> 3) & 1, q1 = (s >> 2) & 1, q2 = (s >> 1) & 1, q3 = s & 1;
                ph[s] = (q0 ? w0 : -w0) + (q1 ? w1 : -w1) + (q2 ? w2 : -w2) + (q3 ? w3 : -w3);
            }
            for (int p = 0; p < 2; p++)
                for (int k = 0; k < 4; k++) {
                    float a0 = ph[p * 8 + k * 2], a1 = ph[p * 8 + k * 2 + 1];
                    g_d1[p * 12 + k]     = make_float2(cosf(a0), cosf(a1));
                    g_d1[p * 12 + 4 + k] = make_float2(sinf(a0), sinf(a1));
                    g_d1[p * 12 + 8 + k] = make_float2(-sinf(a0), -sinf(a1));
                }
        }
        // ---- Dc2: Domega(1b) pushed through the ring, merged with Dphi(2b) ----
        {
            // ring basis map: q1^=q0; q2^=q1; q3^=q2; q0^=q3 (s-encoding: bit3=q0..bit0=q3)
            int inv[16];
            for (int s = 0; s < 16; s++) {
                int q0 = (s >> 3) & 1, q1 = (s >> 2) & 1, q2 = (s >> 1) & 1, q3 = s & 1;
                q1 ^= q0; q2 ^= q1; q3 ^= q2; q0 ^= q3;
                inv[(q0 << 3) | (q1 << 2) | (q2 << 1) | q3] = s;
            }
            float f0 = 0.5f * p2[12 + 0], f1 = 0.5f * p2[12 + 3],
                  f2 = 0.5f * p2[12 + 6], f3 = 0.5f * p2[12 + 9];   // phi of 2b
            float w0 = 0.5f * p2[2], w1 = 0.5f * p2[5],
                  w2 = 0.5f * p2[8], w3 = 0.5f * p2[11];            // omega of 1b
            float ph[16];
            for (int j = 0; j < 16; j++) {
                int q0 = (j >> 3) & 1, q1 = (j >> 2) & 1, q2 = (j >> 1) & 1, q3 = j & 1;
                int i = inv[j];
                int r0 = (i >> 3) & 1, r1 = (i >> 2) & 1, r2 = (i >> 1) & 1, r3 = i & 1;
                ph[j] = (q0 ? f0 : -f0) + (q1 ? f1 : -f1) + (q2 ? f2 : -f2) + (q3 ? f3 : -f3)
                      + (r0 ? w0 : -w0) + (r1 ? w1 : -w1) + (r2 ? w2 : -w2) + (r3 ? w3 : -w3);
            }
            for (int p = 0; p < 2; p++)
                for (int k = 0; k < 4; k++) {
                    float a0 = ph[p * 8 + k * 2], a1 = ph[p * 8 + k * 2 + 1];
                    g_d2[p * 12 + k]     = make_float2(cosf(a0), cosf(a1));
                    g_d2[p * 12 + 4 + k] = make_float2(sinf(a0), sinf(a1));
                    g_d2[p * 12 + 8 + k] = make_float2(-sinf(a0), -sinf(a1));
                }
        }
    }
    if (t == 1) {
        // B-spline bases on [-1,1) collapse to cubics: bs_j(x) = poly/48
        const float BP[4][4] = {
            {1.f, -3.f, 3.f, -1.f},
            {23.f, -15.f, -3.f, 3.f},
            {23.f, 15.f, -3.f, -3.f},
            {1.f, 3.f, 3.f, 1.f}
        };
        const float inv48 = 1.0f / 48.0f;
        for (int o = 0; o < 7; o++) {
            float c0sum = 0.f;
            for (int in = 0; in < 4; in++) {
                float P[4] = {0.f, 0.f, 0.f, 0.f};
                for (int j = 0; j < 4; j++) {
                    float w = spline_w[o * 16 + in * 4 + j] * inv48;
                    for (int k = 0; k < 4; k++) P[k] += w * BP[j][k];
                }
                g_kan[o * 20 + in]      = base_w[o * 4 + in];
                g_kan[o * 20 + 4 + in]  = P[1];
                g_kan[o * 20 + 8 + in]  = P[2];
                g_kan[o * 20 + 12 + in] = P[3];
                c0sum += P[0];
            }
            g_kan[o * 20 + 16] = c0sum;
        }
    }
}

// ---------------- split-state gates (round-4 layout) ----------------
// thread bit p = q0; regs k: bit1=q1, bit0=q2; f32x2 lane = q3. State R[4], I[4].

struct RYC {
    ull cc0, ss0;           // q0: ss0 sign-adjusted for p
    ull cc1, ss1, ns1;      // q1
    ull cc2, ss2, ns2;      // q2
    ull cc3, sm3;           // q3 (lane-mixed (-s, s))
};

__device__ __forceinline__ void ry4(ull* R, ull* I, const RYC& c) {
    // q0 (thread axis)
    {
        ull PR0 = SHFL64(R[0]), PR1 = SHFL64(R[1]), PR2 = SHFL64(R[2]), PR3 = SHFL64(R[3]);
        ull PI0 = SHFL64(I[0]), PI1 = SHFL64(I[1]), PI2 = SHFL64(I[2]), PI3 = SHFL64(I[3]);
        R[0] = F2FMA(c.ss0, PR0, F2MUL(c.cc0, R[0]));
        R[1] = F2FMA(c.ss0, PR1, F2MUL(c.cc0, R[1]));
        R[2] = F2FMA(c.ss0, PR2, F2MUL(c.cc0, R[2]));
        R[3] = F2FMA(c.ss0, PR3, F2MUL(c.cc0, R[3]));
        I[0] = F2FMA(c.ss0, PI0, F2MUL(c.cc0, I[0]));
        I[1] = F2FMA(c.ss0, PI1, F2MUL(c.cc0, I[1]));
        I[2] = F2FMA(c.ss0, PI2, F2MUL(c.cc0, I[2]));
        I[3] = F2FMA(c.ss0, PI3, F2MUL(c.cc0, I[3]));
    }
    // q1: pairs (0,2),(1,3)
    {
        ull a, b;
        a = R[0]; b = R[2]; R[0] = F2FMA(c.ns1, b, F2MUL(c.cc1, a)); R[2] = F2FMA(c.ss1, a, F2MUL(c.cc1, b));
        a = R[1]; b = R[3]; R[1] = F2FMA(c.ns1, b, F2MUL(c.cc1, a)); R[3] = F2FMA(c.ss1, a, F2MUL(c.cc1, b));
        a = I[0]; b = I[2]; I[0] = F2FMA(c.ns1, b, F2MUL(c.cc1, a)); I[2] = F2FMA(c.ss1, a, F2MUL(c.cc1, b));
        a = I[1]; b = I[3]; I[1] = F2FMA(c.ns1, b, F2MUL(c.cc1, a)); I[3] = F2FMA(c.ss1, a, F2MUL(c.cc1, b));
    }
    // q2: pairs (0,1),(2,3)
    {
        ull a, b;
        a = R[0]; b = R[1]; R[0] = F2FMA(c.ns2, b, F2MUL(c.cc2, a)); R[1] = F2FMA(c.ss2, a, F2MUL(c.cc2, b));
        a = R[2]; b = R[3]; R[2] = F2FMA(c.ns2, b, F2MUL(c.cc2, a)); R[3] = F2FMA(c.ss2, a, F2MUL(c.cc2, b));
        a = I[0]; b = I[1]; I[0] = F2FMA(c.ns2, b, F2MUL(c.cc2, a)); I[1] = F2FMA(c.ss2, a, F2MUL(c.cc2, b));
        a = I[2]; b = I[3]; I[2] = F2FMA(c.ns2, b, F2MUL(c.cc2, a)); I[3] = F2FMA(c.ss2, a, F2MUL(c.cc2, b));
    }
    // q3 (lane axis)
#pragma unroll
    for (int k = 0; k < 4; k++) {
        ull v = R[k]; R[k] = F2FMA(c.sm3, SWAPH(v), F2MUL(c.cc3, v));
        ull w = I[k]; I[k] = F2FMA(c.sm3, SWAPH(w), F2MUL(c.cc3, w));
    }
}

__device__ __forceinline__ void diag_apply(ull* R, ull* I, const ull* d) {
#pragma unroll
    for (int k = 0; k < 4; k++) {
        ull C = d[k], S = d[4 + k], nS = d[8 + k];
        ull r = R[k], im = I[k];
        R[k] = F2FMA(nS, im, F2MUL(C, r));
        I[k] = F2FMA(S, r, F2MUL(C, im));
    }
}

// L2a general layer (round-4 format/code)
__device__ __forceinline__ void layer_l2a(ull* R, ull* I, const ull* m, int p) {
    // rot q0
    {
        const ull* mq = m + p * 6;
        ull pr0 = SHFL64(R[0]), pr1 = SHFL64(R[1]), pr2 = SHFL64(R[2]), pr3 = SHFL64(R[3]);
        ull pi0 = SHFL64(I[0]), pi1 = SHFL64(I[1]), pi2 = SHFL64(I[2]), pi3 = SHFL64(I[3]);
        ull PR[4] = {pr0, pr1, pr2, pr3};
        ull PI[4] = {pi0, pi1, pi2, pi3};
        ull m0 = mq[0], m1 = mq[1], m2 = mq[2], m3 = mq[3], m4 = mq[4], m5 = mq[5];
#pragma unroll
        for (int k = 0; k < 4; k++) {
            ull xsr = R[k], xsi = I[k], xpr = PR[k], xpi = PI[k];
            ull t = F2MUL(m0, xsr); t = F2FMA(m1, xsi, t); t = F2FMA(m3, xpr, t); t = F2FMA(m4, xpi, t);
            ull u = F2MUL(m0, xsi); u = F2FMA(m2, xsr, u); u = F2FMA(m3, xpi, u); u = F2FMA(m5, xpr, u);
            R[k] = t; I[k] = u;
        }
    }
    // rot q1: pairs (0,2),(1,3)
    {
        const ull* q = m + 12;
#pragma unroll
        for (int k = 0; k < 2; k++) {
            const int j = k + 2;
            ull x0r = R[k], x0i = I[k], x1r = R[j], x1i = I[j];
            ull t;
            t = F2MUL(q[0], x0r); t = F2FMA(q[1], x0i, t); t = F2FMA(q[2], x1r, t); t = F2FMA(q[3], x1i, t); R[k] = t;
            t = F2MUL(q[0], x0i); t = F2FMA(q[4], x0r, t); t = F2FMA(q[2], x1i, t); t = F2FMA(q[5], x1r, t); I[k] = t;
            t = F2MUL(q[6], x0r); t = F2FMA(q[7], x0i, t); t = F2FMA(q[8], x1r, t); t = F2FMA(q[9], x1i, t); R[j] = t;
            t = F2MUL(q[6], x0i); t = F2FMA(q[10], x0r, t); t = F2FMA(q[8], x1i, t); t = F2FMA(q[11], x1r, t); I[j] = t;
        }
    }
    // rot q2: pairs (0,1),(2,3)
    {
        const ull* q = m + 24;
#pragma unroll
        for (int k = 0; k < 4; k += 2) {
            const int j = k + 1;
            ull x0r = R[k], x0i = I[k], x1r = R[j], x1i = I[j];
            ull t;
            t = F2MUL(q[0], x0r); t = F2FMA(q[1], x0i, t); t = F2FMA(q[2], x1r, t); t = F2FMA(q[3], x1i, t); R[k] = t;
            t = F2MUL(q[0], x0i); t = F2FMA(q[4], x0r, t); t = F2FMA(q[2], x1i, t); t = F2FMA(q[5], x1r, t); I[k] = t;
            t = F2MUL(q[6], x0r); t = F2FMA(q[7], x0i, t); t = F2FMA(q[8], x1r, t); t = F2FMA(q[9], x1i, t); R[j] = t;
            t = F2MUL(q[6], x0i); t = F2FMA(q[10], x0r, t); t = F2FMA(q[8], x1i, t); t = F2FMA(q[11], x1r, t); I[j] = t;
        }
    }
    // rot q3 (lane axis)
    {
        const ull* q = m + 36;
        ull c0 = q[0], c1 = q[1], c2 = q[2], c3 = q[3], c4 = q[4], c5 = q[5];
#pragma unroll
        for (int k = 0; k < 4; k++) {
            ull pr = R[k], pi = I[k];
            ull prs = SWAPH(pr), pis = SWAPH(pi);
            ull t = F2MUL(c0, pr); t = F2FMA(c1, prs, t); t = F2FMA(c2, pi, t); t = F2FMA(c3, pis, t);
            ull u = F2MUL(c4, pr); u = F2FMA(c5, prs, u); u = F2FMA(c0, pi, u); u = F2FMA(c1, pis, u);
            R[k] = t; I[k] = u;
        }
    }
}

// normal ring: CNOT(q0,q1)(q1,q2)(q2,q3)(q3,q0)  [round-4 verified]
__device__ __forceinline__ void ring_normal(ull* R, ull* I, int p) {
    {
        ull r0 = R[0], r1 = R[1], r2 = R[2], r3 = R[3];
        R[0] = p ? r2 : r0; R[2] = p ? r0 : r2;
        R[1] = p ? r3 : r1; R[3] = p ? r1 : r3;
        ull i0 = I[0], i1 = I[1], i2 = I[2], i3 = I[3];
        I[0] = p ? i2 : i0; I[2] = p ? i0 : i2;
        I[1] = p ? i3 : i1; I[3] = p ? i1 : i3;
    }
    { ull t = R[2]; R[2] = R[3]; R[3] = t; t = I[2]; I[2] = I[3]; I[3] = t; }
    R[1] = SWAPH(R[1]); R[3] = SWAPH(R[3]);
    I[1] = SWAPH(I[1]); I[3] = SWAPH(I[3]);
#pragma unroll
    for (int k = 0; k < 4; k++) { R[k] = HIXCH(R[k]); I[k] = HIXCH(I[k]); }
}

// reversed ring: C(1,0) C(2,1) C(3,2) C(0,3)  [round-4 verified]
__device__ __forceinline__ void ring_rev(ull* R, ull* I, int p) {
    R[2] = SHFL64(R[2]); R[3] = SHFL64(R[3]);
    I[2] = SHFL64(I[2]); I[3] = SHFL64(I[3]);
    { ull t = R[1]; R[1] = R[3]; R[3] = t; t = I[1]; I[1] = I[3]; I[3] = t; }
    {
        ull a = R[0], b = R[1]; R[0] = MIXLH(a, b); R[1] = MIXLH(b, a);
        ull c = R[2], d = R[3]; R[2] = MIXLH(c, d); R[3] = MIXLH(d, c);
        ull e = I[0], f = I[1]; I[0] = MIXLH(e, f); I[1] = MIXLH(f, e);
        ull g = I[2], h = I[3]; I[2] = MIXLH(g, h); I[3] = MIXLH(h, g);
    }
#pragma unroll
    for (int k = 0; k < 4; k++) {
        R[k] = p ? SWAPH(R[k]) : R[k];
        I[k] = p ? SWAPH(I[k]) : I[k];
    }
}

// fused feature-map phases for this thread's half [round-4 verified]
__device__ __forceinline__ void phases8(const float* ang, int p, float* ph) {
    float b0 = 0.5f * ang[0], b1 = 0.5f * ang[1], b2 = 0.5f * ang[2], b3 = 0.5f * ang[3];
    float b4 = 0.5f * ang[4], b5 = 0.5f * ang[5], b6 = 0.5f * ang[6];
    float t01 = b0 + b1, d01 = b0 - b1;
    float uA = p ? (d01 + b4) : (-t01 - b4);
    float uB = p ? (t01 - b4) : (-d01 + b4);
    float t23 = b2 + b3, d23 = b2 - b3;
    float e00 = -t23 - b6, e01 = -d23 + b6, e10 = d23 + b6, e11 = t23 - b6;
    ph[0] = uA + (e00 - b5); ph[1] = uA + (e01 - b5);
    ph[2] = uA + (e10 + b5); ph[3] = uA + (e11 + b5);
    ph[4] = uB + (e00 + b5); ph[5] = uB + (e01 + b5);
    ph[6] = uB + (e10 - b5); ph[7] = uB + (e11 - b5);
}

__device__ __forceinline__ void qcell(const float* h_ang, const float* x_ang,
                                      const ull* s_l2a, const ull* d1, const ull* d2,
                                      const float* off1, const float* off2,
                                      const RYC& ry0, const RYC& ry1, const RYC& ry2,
                                      int p, float sgnp, float* ev) {
    ull R[4], I[4];
    float ph[8];

    // D1 (data + const Dphi_1a offsets) on uniform state
    phases8(h_ang, p, ph);
#pragma unroll
    for (int s = 0; s < 8; s++) ph[s] += off1[s];
#pragma unroll
    for (int k = 0; k < 4; k++) {
        float s0, c0, s1, c1;
        __sincosf(ph[2 * k], &s0, &c0);
        __sincosf(ph[2 * k + 1], &s1, &c1);
        R[k] = PACK2(c0, c1); I[k] = PACK2(s0, s1);
    }

    // ansatz 1
    ry4(R, I, ry0);               // RY block of layer 1a
    diag_apply(R, I, d1);         // Domega_1a
    ring_normal(R, I, p);
    layer_l2a(R, I, s_l2a, p);    // H-folded general layer 2a
    ring_rev(R, I, p);

    // D2 (data + const Dphi_1b offsets)
    phases8(x_ang, p, ph);
#pragma unroll
    for (int s = 0; s < 8; s++) ph[s] += off2[s];
#pragma unroll
    for (int k = 0; k < 4; k++) {
        float s0, c0, s1, c1;
        __sincosf(ph[2 * k], &s0, &c0);
        __sincosf(ph[2 * k + 1], &s1, &c1);
        ull c = PACK2(c0, c1), s = PACK2(s0, s1);
        ull nr = F2SUB(F2MUL(c, R[k]), F2MUL(s, I[k]));
        I[k] = F2FMA(s, R[k], F2MUL(c, I[k]));
        R[k] = nr;
    }

    // ansatz 2
    ry4(R, I, ry1);               // RY block of layer 1b
    ring_normal(R, I, p);
    diag_apply(R, I, d2);         // Domega_1b (through ring) * Dphi_2b
    ry4(R, I, ry2);               // RY block of layer 2b (Domega_2b dropped: pure phase)

    // measurement (ring4 folded into parities) [round-4 verified]
    float sv[4], dv[4];
#pragma unroll
    for (int k = 0; k < 4; k++) {
        ull P = F2FMA(I[k], I[k], F2MUL(R[k], R[k]));
        float2 f = UNPK(P);
        sv[k] = f.x + f.y;
        dv[k] = f.x - f.y;
    }
    float A = dv[0] - dv[1] - dv[2] + dv[3];
    float C = sv[0] + sv[1] - sv[2] - sv[3];
    float D = sv[0] - sv[1] - sv[2] + sv[3];
    float Ax = __shfl_xor_sync(0xFFFFFFFFu, A, 1);
    float Cx = __shfl_xor_sync(0xFFFFFFFFu, C, 1);
    float Dx = __shfl_xor_sync(0xFFFFFFFFu, D, 1);
    const float sc = 1.0f / 16.0f;
    ev[0] = (A + Ax) * sc;
    ev[1] = sgnp * (C - Cx) * sc;
    ev[2] = sgnp * (D - Dx) * sc;
    ev[3] = sgnp * (A - Ax) * sc;
}

__device__ __forceinline__ void kan_f(const float* hid, const float* W, float* oang) {
    float sl[4], x2[4], x3[4];
#pragma unroll
    for (int in = 0; in < 4; in++) {
        float x = hid[in];
        float e = __expf(-x);
        sl[in] = __fdividef(x, 1.0f + e);
        x2[in] = x * x;
        x3[in] = x2[in] * x;
    }
#pragma unroll
    for (int o = 0; o < 7; o++) {
        const float* w = W + o * 20;
        float acc = w[16];
#pragma unroll
        for (int in = 0; in < 4; in++) acc = fmaf(w[in], sl[in], acc);
#pragma unroll
        for (int in = 0; in < 4; in++) acc = fmaf(w[4 + in], hid[in], acc);
#pragma unroll
        for (int in = 0; in < 4; in++) acc = fmaf(w[8 + in], x2[in], acc);
#pragma unroll
        for (int in = 0; in < 4; in++) acc = fmaf(w[12 + in], x3[in], acc);
        oang[o] = acc;
    }
}

__global__ void __launch_bounds__(128, 2) qrnn_kernel(
    const float* __restrict__ inputs,      // [B, S, 4]
    const float* __restrict__ initial_t,   // [B, 7]
    const float* __restrict__ cw1,         // [16, 4]
    const float* __restrict__ cb1,         // [16]
    const float* __restrict__ cw2,         // [1, 16]
    const float* __restrict__ cb2,         // [1]
    float* __restrict__ out)               // [B]
{
    __shared__ __align__(16) ull s_l2a[42];
    __shared__ __align__(16) ull s_d1[24];
    __shared__ __align__(16) ull s_d2[24];
    __shared__ float s_kan[140];
    int tid = threadIdx.x;
    {
        const ull* a = reinterpret_cast<const ull*>(g_l2a);
        const ull* b = reinterpret_cast<const ull*>(g_d1);
        const ull* c = reinterpret_cast<const ull*>(g_d2);
        if (tid < 42) s_l2a[tid] = a[tid];
        if (tid >= 42 && tid < 66) s_d1[tid - 42] = b[tid - 42];
        if (tid >= 66 && tid < 90) s_d2[tid - 66] = c[tid - 66];
        for (int i = tid; i < 140; i += 128) s_kan[i] = g_kan[i];
    }
    __syncthreads();

    int gtid = blockIdx.x * blockDim.x + tid;
    int e = gtid >> 1;           // element index
    int p = gtid & 1;            // q0 parity held by this thread
    float sgnp = p ? -1.0f : 1.0f;

    // per-thread constant setup (once)
    float off1[8], off2[8];
#pragma unroll
    for (int s = 0; s < 8; s++) {
        off1[s] = g_off[p * 8 + s];
        off2[s] = g_off[16 + p * 8 + s];
    }
    RYC ry[3];
#pragma unroll
    for (int m = 0; m < 3; m++) {
        float c0 = g_ryf[m * 8 + 0], s0 = g_ryf[m * 8 + 1];
        float c1 = g_ryf[m * 8 + 2], s1 = g_ryf[m * 8 + 3];
        float c2 = g_ryf[m * 8 + 4], s2 = g_ryf[m * 8 + 5];
        float c3 = g_ryf[m * 8 + 6], s3 = g_ryf[m * 8 + 7];
        float s0p = p ? s0 : -s0;
        ry[m].cc0 = PACK2(c0, c0); ry[m].ss0 = PACK2(s0p, s0p);
        ry[m].cc1 = PACK2(c1, c1); ry[m].ss1 = PACK2(s1, s1); ry[m].ns1 = PACK2(-s1, -s1);
        ry[m].cc2 = PACK2(c2, c2); ry[m].ss2 = PACK2(s2, s2); ry[m].ns2 = PACK2(-s2, -s2);
        ry[m].cc3 = PACK2(c3, c3); ry[m].sm3 = PACK2(-s3, s3);
    }
    const ull* d1 = s_d1 + p * 12;
    const ull* d2 = s_d2 + p * 12;

    float h_ang[7];
#pragma unroll
    for (int k = 0; k < 7; k++) h_ang[k] = initial_t[e * 7 + k];

    const float4* inp = reinterpret_cast<const float4*>(inputs) + (size_t)e * SLEN;

    float hid[4];
#pragma unroll 1
    for (int t = 0; t < SLEN; t++) {
        float4 xv = inp[t];
        float x_ang[7];
        x_ang[0] = xv.x; x_ang[1] = xv.y; x_ang[2] = xv.z; x_ang[3] = xv.w;
        x_ang[4] = (PI_F - xv.x) * (PI_F - xv.y);
        x_ang[5] = (PI_F - xv.y) * (PI_F - xv.z);
        x_ang[6] = (PI_F - xv.z) * (PI_F - xv.w);
        if (t > 0) kan_f(hid, s_kan, h_ang);
        qcell(h_ang, x_ang, s_l2a, d1, d2, off1, off2, ry[0], ry[1], ry[2], p, sgnp, hid);
    }

    float o = cb2[0];
#pragma unroll 1
    for (int k = 0; k < 16; k++) {
        float a = cb1[k];
        a = fmaf(cw1[k * 4 + 0], hid[0], a);
        a = fmaf(cw1[k * 4 + 1], hid[1], a);
        a = fmaf(cw1[k * 4 + 2], hid[2], a);
        a = fmaf(cw1[k * 4 + 3], hid[3], a);
        o = fmaf(cw2[k], fmaxf(a, 0.0f), o);
    }
    if (p == 0) out[e] = o;
}

extern "C" void kernel_launch(void* const* d_in, const int* in_sizes, int n_in,
                              void* d_out, int out_size) {
    const float* inputs    = (const float*)d_in[0];
    const float* initial_t = (const float*)d_in[1];
    const float* p1        = (const float*)d_in[2];
    const float* p2        = (const float*)d_in[3];
    const float* base_w    = (const float*)d_in[4];
    const float* spline_w  = (const float*)d_in[5];
    const float* cw1       = (const float*)d_in[6];
    const float* cb1       = (const float*)d_in[7];
    const float* cw2       = (const float*)d_in[8];
    const float* cb2       = (const float*)d_in[9];

    setup_kernel<<<1, 32>>>(p1, p2, base_w, spline_w);
    qrnn_kernel<<<(BATCH * 2) / 128, 128>>>(inputs, initial_t,
                                            cw1, cb1, cw2, cb2, (float*)d_out);
}

// round 8
// speedup vs baseline: 1.0065x; 1.0065x over previous
#include <cuda_runtime.h>
#include <math.h>

#define SLEN 256
#define BATCH 16384
#define PI_F 3.14159265358979323846f
#define R2_F 0.70710678118654752440f

typedef unsigned long long ull;

// ---------- packed f32x2 primitives ----------
__device__ __forceinline__ ull F2MUL(ull a, ull b) {
    ull d; asm("mul.rn.f32x2 %0,%1,%2;" : "=l"(d) : "l"(a), "l"(b)); return d;
}
__device__ __forceinline__ ull F2FMA(ull a, ull b, ull c) {
    ull d; asm("fma.rn.f32x2 %0,%1,%2,%3;" : "=l"(d) : "l"(a), "l"(b), "l"(c)); return d;
}
__device__ __forceinline__ ull F2SUB(ull a, ull b) {
    ull d; asm("sub.rn.f32x2 %0,%1,%2;" : "=l"(d) : "l"(a), "l"(b)); return d;
}
__device__ __forceinline__ ull PACK2(float lo, float hi) {
    ull d; asm("mov.b64 %0,{%1,%2};" : "=l"(d) : "f"(lo), "f"(hi)); return d;
}
__device__ __forceinline__ float2 UNPK(ull v) {
    float2 r; asm("mov.b64 {%0,%1},%2;" : "=f"(r.x), "=f"(r.y) : "l"(v)); return r;
}
__device__ __forceinline__ ull SWAPH(ull v) {
    float2 r = UNPK(v); return PACK2(r.y, r.x);
}
__device__ __forceinline__ ull MIXLH(ull a, ull b) {   // (a.lo, b.hi)
    float2 x = UNPK(a), y = UNPK(b); return PACK2(x.x, y.y);
}
__device__ __forceinline__ ull SHFL64(ull v) {
    return __shfl_xor_sync(0xFFFFFFFFu, v, 1);
}

// ---------- precomputed constants ----------
// L2a layout (42 ull):
//  [0..5]   q0 PREMIXED consts p=0: A0,A1,A2,A3,C2,C5  (absorb deferred HIXCH)
//  [6..11]  q0 PREMIXED consts p=1
//  [12..23] q1-rot generic 12-slot (lane-dup)
//  [24..35] q2-rot generic 12-slot (lane-dup)
//  [36..41] q3-rot lane-mixed
__device__ float2 g_l2a[42];
// d1: plain diag (omega 1a): [p][C0..3|S0..3|nS0..3]
__device__ float2 g_d1[24];
// d2m: PREMIXED diag (omega1b∘ring * phi2b): lo lane from p, hi lane from 1-p
__device__ float2 g_d2m[24];
// phase offsets: [diag 0/1][slot s=q0*8+q1*4+q2*2+q3]
__device__ float g_off[32];
// RY coefs: [layer m=0(1a),1(1b),2(2b)][q][c,s]
__device__ float g_ryf[24];
// KAN folded weights
__device__ float g_kan[140];

__global__ void setup_kernel(const float* __restrict__ p1, const float* __restrict__ p2,
                             const float* __restrict__ base_w, const float* __restrict__ spline_w) {
    int t = threadIdx.x;
    if (t == 0) {
        // ---- L2a: a=0, l=1 rots with H fold ----
        for (int q = 0; q < 4; q++) {
            float phi = p1[12 + q * 3 + 0];
            float th  = p1[12 + q * 3 + 1];
            float om  = p1[12 + q * 3 + 2];
            float st, ct; sincosf(0.5f * th, &st, &ct);
            float sp, cp; sincosf(0.5f * (phi + om), &sp, &cp);
            float sm, cm; sincosf(0.5f * (phi - om), &sm, &cm);
            float ar =  cp * ct, ai = -sp * ct;
            float br = -cm * st, bi = -sm * st;
            float dr =  cm * st, di = -sm * st;
            float er =  cp * ct, ei =  sp * ct;
            // fold inter-ansatz H: Rot' = H @ Rot
            float nar = (ar + dr) * R2_F, nai = (ai + di) * R2_F;
            float nbr = (br + er) * R2_F, nbi = (bi + ei) * R2_F;
            float ndr = (ar - dr) * R2_F, ndi = (ai - di) * R2_F;
            float ner = (br - er) * R2_F, nei = (bi - ei) * R2_F;
            ar = nar; ai = nai; br = nbr; bi = nbi;
            dr = ndr; di = ndi; er = ner; ei = nei;
            float2* base = g_l2a;
            if (q == 0) {
                // rows[p] = {m0..m5} = {self_r, -self_i, self_i, part_r, -part_i, part_i}
                float rows[2][6] = {
                    { ar, -ai, ai, br, -bi, bi },
                    { er, -ei, ei, dr, -di, di }
                };
                for (int p = 0; p < 2; p++) {
                    const float* m = rows[p];
                    float2* o = base + p * 6;
                    o[0] = make_float2(m[0], m[3]);   // A0
                    o[1] = make_float2(m[1], m[4]);   // A1
                    o[2] = make_float2(m[3], m[0]);   // A2
                    o[3] = make_float2(m[4], m[1]);   // A3
                    o[4] = make_float2(m[2], m[5]);   // C2
                    o[5] = make_float2(m[5], m[2]);   // C5
                }
            } else if (q == 1 || q == 2) {
                float2* o = base + (q == 1 ? 12 : 24);
                o[0]  = make_float2(ar, ar);   o[1]  = make_float2(-ai, -ai);
                o[2]  = make_float2(br, br);   o[3]  = make_float2(-bi, -bi);
                o[4]  = make_float2(ai, ai);   o[5]  = make_float2(bi, bi);
                o[6]  = make_float2(dr, dr);   o[7]  = make_float2(-di, -di);
                o[8]  = make_float2(er, er);   o[9]  = make_float2(-ei, -ei);
                o[10] = make_float2(di, di);   o[11] = make_float2(ei, ei);
            } else {
                float2* o = base + 36;
                o[0] = make_float2(ar, er);
                o[1] = make_float2(br, dr);
                o[2] = make_float2(-ai, -ei);
                o[3] = make_float2(-bi, -di);
                o[4] = make_float2(ai, ei);
                o[5] = make_float2(bi, di);
            }
        }
        // ---- RY coefficients for layers 1a(a0l0), 1b(a1l0), 2b(a1l1) ----
        for (int m = 0; m < 3; m++) {
            int a = (m == 0) ? 0 : 1;
            int l = (m == 2) ? 1 : 0;
            const float* pp = a ? p2 : p1;
            for (int q = 0; q < 4; q++) {
                float th = pp[l * 12 + q * 3 + 1];
                g_ryf[m * 8 + q * 2 + 0] = cosf(0.5f * th);
                g_ryf[m * 8 + q * 2 + 1] = sinf(0.5f * th);
            }
        }
        // ---- phase offsets: Dphi of 1a (into D1) and of 1b (into D2) ----
        for (int d = 0; d < 2; d++) {
            const float* pp = d ? p2 : p1;   // phi of layer (a=d, l=0)
            float f0 = 0.5f * pp[0], f1 = 0.5f * pp[3], f2 = 0.5f * pp[6], f3 = 0.5f * pp[9];
            for (int s = 0; s < 16; s++) {
                int q0 = (s >> 3) & 1, q1 = (s >> 2) & 1, q2 = (s >> 1) & 1, q3 = s & 1;
                g_off[d * 16 + s] = (q0 ? f0 : -f0) + (q1 ? f1 : -f1)
                                  + (q2 ? f2 : -f2) + (q3 ? f3 : -f3);
            }
        }
        // ---- d1: Domega of 1a (plain) ----
        {
            float w0 = 0.5f * p1[2], w1 = 0.5f * p1[5], w2 = 0.5f * p1[8], w3 = 0.5f * p1[11];
            float ph[16];
            for (int s = 0; s < 16; s++) {
                int q0 = (s >> 3) & 1, q1 = (s >> 2) & 1, q2 = (s >> 1) & 1, q3 = s & 1;
                ph[s] = (q0 ? w0 : -w0) + (q1 ? w1 : -w1) + (q2 ? w2 : -w2) + (q3 ? w3 : -w3);
            }
            for (int p = 0; p < 2; p++)
                for (int k = 0; k < 4; k++) {
                    float a0 = ph[p * 8 + k * 2], a1 = ph[p * 8 + k * 2 + 1];
                    g_d1[p * 12 + k]     = make_float2(cosf(a0), cosf(a1));
                    g_d1[p * 12 + 4 + k] = make_float2(sinf(a0), sinf(a1));
                    g_d1[p * 12 + 8 + k] = make_float2(-sinf(a0), -sinf(a1));
                }
        }
        // ---- d2m: Domega(1b) through ring * Dphi(2b), hi-lane PREMIXED across p ----
        {
            int inv[16];
            for (int s = 0; s < 16; s++) {
                int q0 = (s >> 3) & 1, q1 = (s >> 2) & 1, q2 = (s >> 1) & 1, q3 = s & 1;
                q1 ^= q0; q2 ^= q1; q3 ^= q2; q0 ^= q3;
                inv[(q0 << 3) | (q1 << 2) | (q2 << 1) | q3] = s;
            }
            float f0 = 0.5f * p2[12 + 0], f1 = 0.5f * p2[12 + 3],
                  f2 = 0.5f * p2[12 + 6], f3 = 0.5f * p2[12 + 9];   // phi of 2b
            float w0 = 0.5f * p2[2], w1 = 0.5f * p2[5],
                  w2 = 0.5f * p2[8], w3 = 0.5f * p2[11];            // omega of 1b
            float ph[16];
            for (int j = 0; j < 16; j++) {
                int q0 = (j >> 3) & 1, q1 = (j >> 2) & 1, q2 = (j >> 1) & 1, q3 = j & 1;
                int i = inv[j];
                int r0 = (i >> 3) & 1, r1 = (i >> 2) & 1, r2 = (i >> 1) & 1, r3 = i & 1;
                ph[j] = (q0 ? f0 : -f0) + (q1 ? f1 : -f1) + (q2 ? f2 : -f2) + (q3 ? f3 : -f3)
                      + (r0 ? w0 : -w0) + (r1 ? w1 : -w1) + (r2 ? w2 : -w2) + (r3 ? w3 : -w3);
            }
            for (int p = 0; p < 2; p++)
                for (int k = 0; k < 4; k++) {
                    // lo lane = true phase of thread p; hi lane = true phase of thread 1-p
                    float a0 = ph[p * 8 + k * 2], a1 = ph[(1 - p) * 8 + k * 2 + 1];
                    g_d2m[p * 12 + k]     = make_float2(cosf(a0), cosf(a1));
                    g_d2m[p * 12 + 4 + k] = make_float2(sinf(a0), sinf(a1));
                    g_d2m[p * 12 + 8 + k] = make_float2(-sinf(a0), -sinf(a1));
                }
        }
    }
    if (t == 1) {
        // B-spline bases on [-1,1) collapse to cubics: bs_j(x) = poly/48
        const float BP[4][4] = {
            {1.f, -3.f, 3.f, -1.f},
            {23.f, -15.f, -3.f, 3.f},
            {23.f, 15.f, -3.f, -3.f},
            {1.f, 3.f, 3.f, 1.f}
        };
        const float inv48 = 1.0f / 48.0f;
        for (int o = 0; o < 7; o++) {
            float c0sum = 0.f;
            for (int in = 0; in < 4; in++) {
                float P[4] = {0.f, 0.f, 0.f, 0.f};
                for (int j = 0; j < 4; j++) {
                    float w = spline_w[o * 16 + in * 4 + j] * inv48;
                    for (int k = 0; k < 4; k++) P[k] += w * BP[j][k];
                }
                g_kan[o * 20 + in]      = base_w[o * 4 + in];
                g_kan[o * 20 + 4 + in]  = P[1];
                g_kan[o * 20 + 8 + in]  = P[2];
                g_kan[o * 20 + 12 + in] = P[3];
                c0sum += P[0];
            }
            g_kan[o * 20 + 16] = c0sum;
        }
    }
}

// ---------------- split-state gates ----------------
// thread bit p = q0; regs k: bit1=q1, bit0=q2; f32x2 lane = q3. State R[4], I[4].
// "Mixed" rep after a skipped HIXCH: own reg = (true_p.lo, true_{1-p}.hi).

struct RYC {
    ull D0, D1;             // q0 sweep consts (plain: lane-dup; fused: lane-mixed)
    ull cc1, ss1, ns1;      // q1
    ull cc2, ss2, ns2;      // q2
    ull cc3, sm3;           // q3 (lane-mixed (-s, s))
};

struct L2AC {               // register-hoisted l2a q0 (premixed) + q3 consts
    ull a0, a1, a2, a3, c2, c5;
    ull t0, t1, t2, t3, t4, t5;
};

__device__ __forceinline__ void ry4(ull* R, ull* I, const RYC& c) {
    // q0 (thread axis): out = D0 (.) mine + D1 (.) shfl
    {
        ull PR0 = SHFL64(R[0]), PR1 = SHFL64(R[1]), PR2 = SHFL64(R[2]), PR3 = SHFL64(R[3]);
        ull PI0 = SHFL64(I[0]), PI1 = SHFL64(I[1]), PI2 = SHFL64(I[2]), PI3 = SHFL64(I[3]);
        R[0] = F2FMA(c.D1, PR0, F2MUL(c.D0, R[0]));
        R[1] = F2FMA(c.D1, PR1, F2MUL(c.D0, R[1]));
        R[2] = F2FMA(c.D1, PR2, F2MUL(c.D0, R[2]));
        R[3] = F2FMA(c.D1, PR3, F2MUL(c.D0, R[3]));
        I[0] = F2FMA(c.D1, PI0, F2MUL(c.D0, I[0]));
        I[1] = F2FMA(c.D1, PI1, F2MUL(c.D0, I[1]));
        I[2] = F2FMA(c.D1, PI2, F2MUL(c.D0, I[2]));
        I[3] = F2FMA(c.D1, PI3, F2MUL(c.D0, I[3]));
    }
    // q1: pairs (0,2),(1,3)
    {
        ull a, b;
        a = R[0]; b = R[2]; R[0] = F2FMA(c.ns1, b, F2MUL(c.cc1, a)); R[2] = F2FMA(c.ss1, a, F2MUL(c.cc1, b));
        a = R[1]; b = R[3]; R[1] = F2FMA(c.ns1, b, F2MUL(c.cc1, a)); R[3] = F2FMA(c.ss1, a, F2MUL(c.cc1, b));
        a = I[0]; b = I[2]; I[0] = F2FMA(c.ns1, b, F2MUL(c.cc1, a)); I[2] = F2FMA(c.ss1, a, F2MUL(c.cc1, b));
        a = I[1]; b = I[3]; I[1] = F2FMA(c.ns1, b, F2MUL(c.cc1, a)); I[3] = F2FMA(c.ss1, a, F2MUL(c.cc1, b));
    }
    // q2: pairs (0,1),(2,3)
    {
        ull a, b;
        a = R[0]; b = R[1]; R[0] = F2FMA(c.ns2, b, F2MUL(c.cc2, a)); R[1] = F2FMA(c.ss2, a, F2MUL(c.cc2, b));
        a = R[2]; b = R[3]; R[2] = F2FMA(c.ns2, b, F2MUL(c.cc2, a)); R[3] = F2FMA(c.ss2, a, F2MUL(c.cc2, b));
        a = I[0]; b = I[1]; I[0] = F2FMA(c.ns2, b, F2MUL(c.cc2, a)); I[1] = F2FMA(c.ss2, a, F2MUL(c.cc2, b));
        a = I[2]; b = I[3]; I[2] = F2FMA(c.ns2, b, F2MUL(c.cc2, a)); I[3] = F2FMA(c.ss2, a, F2MUL(c.cc2, b));
    }
    // q3 (lane axis)
#pragma unroll
    for (int k = 0; k < 4; k++) {
        ull v = R[k]; R[k] = F2FMA(c.sm3, SWAPH(v), F2MUL(c.cc3, v));
        ull w = I[k]; I[k] = F2FMA(c.sm3, SWAPH(w), F2MUL(c.cc3, w));
    }
}

__device__ __forceinline__ void diag_apply(ull* R, ull* I, const ull* d) {
#pragma unroll
    for (int k = 0; k < 4; k++) {
        ull C = d[k], S = d[4 + k], nS = d[8 + k];
        ull r = R[k], im = I[k];
        R[k] = F2FMA(nS, im, F2MUL(C, r));
        I[k] = F2FMA(S, r, F2MUL(C, im));
    }
}

// L2a general layer; q0 sweep uses PREMIXED constants absorbing the deferred HIXCH.
// sq12 points at the q1/q2 constants (24 ull) in shared memory.
__device__ __forceinline__ void layer_l2a(ull* R, ull* I, const ull* sq12, const L2AC& C) {
    // rot q0 (fused): input mixed, output TRUE
    {
        ull YR0 = SHFL64(R[0]), YR1 = SHFL64(R[1]), YR2 = SHFL64(R[2]), YR3 = SHFL64(R[3]);
        ull YI0 = SHFL64(I[0]), YI1 = SHFL64(I[1]), YI2 = SHFL64(I[2]), YI3 = SHFL64(I[3]);
        ull YR[4] = {YR0, YR1, YR2, YR3};
        ull YI[4] = {YI0, YI1, YI2, YI3};
#pragma unroll
        for (int k = 0; k < 4; k++) {
            ull xr = R[k], xi = I[k];
            ull t = F2MUL(C.a0, xr); t = F2FMA(C.a1, xi, t); t = F2FMA(C.a2, YR[k], t); t = F2FMA(C.a3, YI[k], t);
            ull u = F2MUL(C.a0, xi); u = F2FMA(C.c2, xr, u); u = F2FMA(C.a2, YI[k], u); u = F2FMA(C.c5, YR[k], u);
            R[k] = t; I[k] = u;
        }
    }
    // rot q1: pairs (0,2),(1,3) — constants sq12[0..11] via LDS128
    {
        const ulonglong2* v = reinterpret_cast<const ulonglong2*>(sq12);
        ulonglong2 v0 = v[0], v1 = v[1], v2 = v[2], v3 = v[3], v4 = v[4], v5 = v[5];
#pragma unroll
        for (int k = 0; k < 2; k++) {
            const int j = k + 2;
            ull x0r = R[k], x0i = I[k], x1r = R[j], x1i = I[j];
            ull t;
            t = F2MUL(v0.x, x0r); t = F2FMA(v0.y, x0i, t); t = F2FMA(v1.x, x1r, t); t = F2FMA(v1.y, x1i, t); R[k] = t;
            t = F2MUL(v0.x, x0i); t = F2FMA(v2.x, x0r, t); t = F2FMA(v1.x, x1i, t); t = F2FMA(v2.y, x1r, t); I[k] = t;
            t = F2MUL(v3.x, x0r); t = F2FMA(v3.y, x0i, t); t = F2FMA(v4.x, x1r, t); t = F2FMA(v4.y, x1i, t); R[j] = t;
            t = F2MUL(v3.x, x0i); t = F2FMA(v5.x, x0r, t); t = F2FMA(v4.x, x1i, t); t = F2FMA(v5.y, x1r, t); I[j] = t;
        }
    }
    // rot q2: pairs (0,1),(2,3) — constants sq12[12..23]
    {
        const ulonglong2* v = reinterpret_cast<const ulonglong2*>(sq12 + 12);
        ulonglong2 v0 = v[0], v1 = v[1], v2 = v[2], v3 = v[3], v4 = v[4], v5 = v[5];
#pragma unroll
        for (int k = 0; k < 4; k += 2) {
            const int j = k + 1;
            ull x0r = R[k], x0i = I[k], x1r = R[j], x1i = I[j];
            ull t;
            t = F2MUL(v0.x, x0r); t = F2FMA(v0.y, x0i, t); t = F2FMA(v1.x, x1r, t); t = F2FMA(v1.y, x1i, t); R[k] = t;
            t = F2MUL(v0.x, x0i); t = F2FMA(v2.x, x0r, t); t = F2FMA(v1.x, x1i, t); t = F2FMA(v2.y, x1r, t); I[k] = t;
            t = F2MUL(v3.x, x0r); t = F2FMA(v3.y, x0i, t); t = F2FMA(v4.x, x1r, t); t = F2FMA(v4.y, x1i, t); R[j] = t;
            t = F2MUL(v3.x, x0i); t = F2FMA(v5.x, x0r, t); t = F2FMA(v4.x, x1i, t); t = F2FMA(v5.y, x1r, t); I[j] = t;
        }
    }
    // rot q3 (lane axis), register-hoisted constants
#pragma unroll
    for (int k = 0; k < 4; k++) {
        ull pr = R[k], pi = I[k];
        ull prs = SWAPH(pr), pis = SWAPH(pi);
        ull t = F2MUL(C.t0, pr); t = F2FMA(C.t1, prs, t); t = F2FMA(C.t2, pi, t); t = F2FMA(C.t3, pis, t);
        ull u = F2MUL(C.t4, pr); u = F2FMA(C.t5, prs, u); u = F2FMA(C.t0, pi, u); u = F2FMA(C.t1, pis, u);
        R[k] = t; I[k] = u;
    }
}

// ring without final HIXCH (deferred into the following q0 sweep / premixed diag)
__device__ __forceinline__ void ring_normal_nox(ull* R, ull* I, int p) {
    // CNOT(q0,q1): p=1 swaps regs 0<->2, 1<->3
    {
        ull r0 = R[0], r1 = R[1], r2 = R[2], r3 = R[3];
        R[0] = p ? r2 : r0; R[2] = p ? r0 : r2;
        R[1] = p ? r3 : r1; R[3] = p ? r1 : r3;
        ull i0 = I[0], i1 = I[1], i2 = I[2], i3 = I[3];
        I[0] = p ? i2 : i0; I[2] = p ? i0 : i2;
        I[1] = p ? i3 : i1; I[3] = p ? i1 : i3;
    }
    // CNOT(q1,q2): swap regs 2,3
    { ull t = R[2]; R[2] = R[3]; R[3] = t; t = I[2]; I[2] = I[3]; I[3] = t; }
    // CNOT(q2,q3): lane swap on regs 1,3
    R[1] = SWAPH(R[1]); R[3] = SWAPH(R[3]);
    I[1] = SWAPH(I[1]); I[3] = SWAPH(I[3]);
    // CNOT(q3,q0): SKIPPED -> state left in mixed representation
}

// reversed ring: C(1,0) C(2,1) C(3,2) C(0,3)  [round-4 verified]
__device__ __forceinline__ void ring_rev(ull* R, ull* I, int p) {
    R[2] = SHFL64(R[2]); R[3] = SHFL64(R[3]);
    I[2] = SHFL64(I[2]); I[3] = SHFL64(I[3]);
    { ull t = R[1]; R[1] = R[3]; R[3] = t; t = I[1]; I[1] = I[3]; I[3] = t; }
    {
        ull a = R[0], b = R[1]; R[0] = MIXLH(a, b); R[1] = MIXLH(b, a);
        ull c = R[2], d = R[3]; R[2] = MIXLH(c, d); R[3] = MIXLH(d, c);
        ull e = I[0], f = I[1]; I[0] = MIXLH(e, f); I[1] = MIXLH(f, e);
        ull g = I[2], h = I[3]; I[2] = MIXLH(g, h); I[3] = MIXLH(h, g);
    }
#pragma unroll
    for (int k = 0; k < 4; k++) {
        R[k] = p ? SWAPH(R[k]) : R[k];
        I[k] = p ? SWAPH(I[k]) : I[k];
    }
}

// fused feature-map phases for this thread's half [round-4 verified]
__device__ __forceinline__ void phases8(const float* ang, int p, float* ph) {
    float b0 = 0.5f * ang[0], b1 = 0.5f * ang[1], b2 = 0.5f * ang[2], b3 = 0.5f * ang[3];
    float b4 = 0.5f * ang[4], b5 = 0.5f * ang[5], b6 = 0.5f * ang[6];
    float t01 = b0 + b1, d01 = b0 - b1;
    float uA = p ? (d01 + b4) : (-t01 - b4);
    float uB = p ? (t01 - b4) : (-d01 + b4);
    float t23 = b2 + b3, d23 = b2 - b3;
    float e00 = -t23 - b6, e01 = -d23 + b6, e10 = d23 + b6, e11 = t23 - b6;
    ph[0] = uA + (e00 - b5); ph[1] = uA + (e01 - b5);
    ph[2] = uA + (e10 + b5); ph[3] = uA + (e11 + b5);
    ph[4] = uB + (e00 + b5); ph[5] = uB + (e01 + b5);
    ph[6] = uB + (e10 - b5); ph[7] = uB + (e11 - b5);
}

__device__ __forceinline__ void qcell(const float* h_ang, const float* x_ang,
                                      const ull* sq12, const L2AC& l2c,
                                      const ull* d1, const ull* d2,
                                      const float* off1, const float* off2,
                                      const RYC& ry0, const RYC& ry1, const RYC& ry2,
                                      int p, float sgnp, float* ev) {
    ull R[4], I[4];
    float ph[8];

    // D1 (data + const Dphi_1a offsets) on uniform state
    phases8(h_ang, p, ph);
#pragma unroll
    for (int s = 0; s < 8; s++) ph[s] += off1[s];
#pragma unroll
    for (int k = 0; k < 4; k++) {
        float s0, c0, s1, c1;
        __sincosf(ph[2 * k], &s0, &c0);
        __sincosf(ph[2 * k + 1], &s1, &c1);
        R[k] = PACK2(c0, c1); I[k] = PACK2(s0, s1);
    }

    // ansatz 1
    ry4(R, I, ry0);                // RY of layer 1a (plain)
    diag_apply(R, I, d1);          // Domega_1a (true rep)
    ring_normal_nox(R, I, p);      // -> mixed rep
    layer_l2a(R, I, sq12, l2c);    // fused q0 restores true rep
    ring_rev(R, I, p);

    // D2 (data + const Dphi_1b offsets)
    phases8(x_ang, p, ph);
#pragma unroll
    for (int s = 0; s < 8; s++) ph[s] += off2[s];
#pragma unroll
    for (int k = 0; k < 4; k++) {
        float s0, c0, s1, c1;
        __sincosf(ph[2 * k], &s0, &c0);
        __sincosf(ph[2 * k + 1], &s1, &c1);
        ull c = PACK2(c0, c1), s = PACK2(s0, s1);
        ull nr = F2SUB(F2MUL(c, R[k]), F2MUL(s, I[k]));
        I[k] = F2FMA(s, R[k], F2MUL(c, I[k]));
        R[k] = nr;
    }

    // ansatz 2
    ry4(R, I, ry1);                // RY of layer 1b (plain, true rep)
    ring_normal_nox(R, I, p);      // -> mixed rep
    diag_apply(R, I, d2);          // PREMIXED Domega_1b∘ring * Dphi_2b (stays mixed)
    ry4(R, I, ry2);                // fused q0 sweep restores true rep

    // measurement (final ring folded into parities) [round-4 verified]
    float sv[4], dv[4];
#pragma unroll
    for (int k = 0; k < 4; k++) {
        ull P = F2FMA(I[k], I[k], F2MUL(R[k], R[k]));
        float2 f = UNPK(P);
        sv[k] = f.x + f.y;
        dv[k] = f.x - f.y;
    }
    float A = dv[0] - dv[1] - dv[2] + dv[3];
    float C = sv[0] + sv[1] - sv[2] - sv[3];
    float D = sv[0] - sv[1] - sv[2] + sv[3];
    float Ax = __shfl_xor_sync(0xFFFFFFFFu, A, 1);
    float Cx = __shfl_xor_sync(0xFFFFFFFFu, C, 1);
    float Dx = __shfl_xor_sync(0xFFFFFFFFu, D, 1);
    const float sc = 1.0f / 16.0f;
    ev[0] = (A + Ax) * sc;
    ev[1] = sgnp * (C - Cx) * sc;
    ev[2] = sgnp * (D - Dx) * sc;
    ev[3] = sgnp * (A - Ax) * sc;
}

__device__ __forceinline__ void kan_f(const float* hid, const float* W, float* oang) {
    float sl[4], x2[4], x3[4];
#pragma unroll
    for (int in = 0; in < 4; in++) {
        float x = hid[in];
        float e = __expf(-x);
        sl[in] = __fdividef(x, 1.0f + e);
        x2[in] = x * x;
        x3[in] = x2[in] * x;
    }
#pragma unroll
    for (int o = 0; o < 7; o++) {
        const float* w = W + o * 20;
        float acc = w[16];
#pragma unroll
        for (int in = 0; in < 4; in++) acc = fmaf(w[in], sl[in], acc);
#pragma unroll
        for (int in = 0; in < 4; in++) acc = fmaf(w[4 + in], hid[in], acc);
#pragma unroll
        for (int in = 0; in < 4; in++) acc = fmaf(w[8 + in], x2[in], acc);
#pragma unroll
        for (int in = 0; in < 4; in++) acc = fmaf(w[12 + in], x3[in], acc);
        oang[o] = acc;
    }
}

__global__ void __launch_bounds__(128, 2) qrnn_kernel(
    const float* __restrict__ inputs,      // [B, S, 4]
    const float* __restrict__ initial_t,   // [B, 7]
    const float* __restrict__ cw1,         // [16, 4]
    const float* __restrict__ cb1,         // [16]
    const float* __restrict__ cw2,         // [1, 16]
    const float* __restrict__ cb2,         // [1]
    float* __restrict__ out)               // [B]
{
    __shared__ __align__(16) ull s_q12[24];   // l2a q1+q2 constants
    __shared__ float s_kan[140];
    int tid = threadIdx.x;
    {
        const ull* a = reinterpret_cast<const ull*>(g_l2a);
        if (tid < 24) s_q12[tid] = a[12 + tid];
        for (int i = tid; i < 140; i += 128) s_kan[i] = g_kan[i];
    }
    __syncthreads();

    int gtid = blockIdx.x * blockDim.x + tid;
    int e = gtid >> 1;           // element index
    int p = gtid & 1;            // q0 parity held by this thread
    float sgnp = p ? -1.0f : 1.0f;

    // per-thread constants (registers)
    float off1[8], off2[8];
#pragma unroll
    for (int s = 0; s < 8; s++) {
        off1[s] = g_off[p * 8 + s];
        off2[s] = g_off[16 + p * 8 + s];
    }
    RYC ry[3];
#pragma unroll
    for (int m = 0; m < 3; m++) {
        float c0 = g_ryf[m * 8 + 0], s0 = g_ryf[m * 8 + 1];
        float c1 = g_ryf[m * 8 + 2], s1 = g_ryf[m * 8 + 3];
        float c2 = g_ryf[m * 8 + 4], s2 = g_ryf[m * 8 + 5];
        float c3 = g_ryf[m * 8 + 6], s3 = g_ryf[m * 8 + 7];
        float s0p = p ? s0 : -s0;
        if (m == 2) {
            // fused q0 sweep (consumes mixed rep): D0=(c,s_p), D1=(s_p,c)
            ry[m].D0 = PACK2(c0, s0p); ry[m].D1 = PACK2(s0p, c0);
        } else {
            ry[m].D0 = PACK2(c0, c0);  ry[m].D1 = PACK2(s0p, s0p);
        }
        ry[m].cc1 = PACK2(c1, c1); ry[m].ss1 = PACK2(s1, s1); ry[m].ns1 = PACK2(-s1, -s1);
        ry[m].cc2 = PACK2(c2, c2); ry[m].ss2 = PACK2(s2, s2); ry[m].ns2 = PACK2(-s2, -s2);
        ry[m].cc3 = PACK2(c3, c3); ry[m].sm3 = PACK2(-s3, s3);
    }
    // hoisted diagonals
    ull d1r[12], d2r[12];
    {
        const ull* b = reinterpret_cast<const ull*>(g_d1) + p * 12;
        const ull* c = reinterpret_cast<const ull*>(g_d2m) + p * 12;
#pragma unroll
        for (int i = 0; i < 12; i++) { d1r[i] = b[i]; d2r[i] = c[i]; }
    }
    // hoisted l2a q0 (premixed, per-parity) + q3 constants
    L2AC l2c;
    {
        const ull* a = reinterpret_cast<const ull*>(g_l2a);
        const ull* mq = a + p * 6;
        l2c.a0 = mq[0]; l2c.a1 = mq[1]; l2c.a2 = mq[2];
        l2c.a3 = mq[3]; l2c.c2 = mq[4]; l2c.c5 = mq[5];
        l2c.t0 = a[36]; l2c.t1 = a[37]; l2c.t2 = a[38];
        l2c.t3 = a[39]; l2c.t4 = a[40]; l2c.t5 = a[41];
    }

    float h_ang[7];
#pragma unroll
    for (int k = 0; k < 7; k++) h_ang[k] = initial_t[e * 7 + k];

    const float4* inp = reinterpret_cast<const float4*>(inputs) + (size_t)e * SLEN;

    float hid[4];
#pragma unroll 1
    for (int t = 0; t < SLEN; t++) {
        float4 xv = inp[t];
        float x_ang[7];
        x_ang[0] = xv.x; x_ang[1] = xv.y; x_ang[2] = xv.z; x_ang[3] = xv.w;
        x_ang[4] = (PI_F - xv.x) * (PI_F - xv.y);
        x_ang[5] = (PI_F - xv.y) * (PI_F - xv.z);
        x_ang[6] = (PI_F - xv.z) * (PI_F - xv.w);
        if (t > 0) kan_f(hid, s_kan, h_ang);
        qcell(h_ang, x_ang, s_q12, l2c, d1r, d2r, off1, off2,
              ry[0], ry[1], ry[2], p, sgnp, hid);
    }

    float o = cb2[0];
#pragma unroll 1
    for (int k = 0; k < 16; k++) {
        float a = cb1[k];
        a = fmaf(cw1[k * 4 + 0], hid[0], a);
        a = fmaf(cw1[k * 4 + 1], hid[1], a);
        a = fmaf(cw1[k * 4 + 2], hid[2], a);
        a = fmaf(cw1[k * 4 + 3], hid[3], a);
        o = fmaf(cw2[k], fmaxf(a, 0.0f), o);
    }
    if (p == 0) out[e] = o;
}

extern "C" void kernel_launch(void* const* d_in, const int* in_sizes, int n_in,
                              void* d_out, int out_size) {
    const float* inputs    = (const float*)d_in[0];
    const float* initial_t = (const float*)d_in[1];
    const float* p1        = (const float*)d_in[2];
    const float* p2        = (const float*)d_in[3];
    const float* base_w    = (const float*)d_in[4];
    const float* spline_w  = (const float*)d_in[5];
    const float* cw1       = (const float*)d_in[6];
    const float* cb1       = (const float*)d_in[7];
    const float* cw2       = (const float*)d_in[8];
    const float* cb2       = (const float*)d_in[9];

    setup_kernel<<<1, 32>>>(p1, p2, base_w, spline_w);
    qrnn_kernel<<<(BATCH * 2) / 128, 128>>>(inputs, initial_t,
                                            cw1, cb1, cw2, cb2, (float*)d_out);
}